// round 2
// baseline (speedup 1.0000x reference)
#include <cuda_runtime.h>

#define D_IN 64
#define D_E 64
#define D_MSG_IN 128   // D_IN + D_E
#define D_OUT 128
#define D_APPLY_IN 192 // D_IN + D_OUT
#define MAX_NODES 50000

// Scratch: aggregated messages per node (L2-resident, 25.6 MB)
__device__ float g_hneigh[MAX_NODES * D_OUT];

// ---------- packed f32x2 helpers (Blackwell fma.rn.f32x2 = 2x fp32 rate) ----------
__device__ __forceinline__ unsigned long long pack2(float x) {
    unsigned long long r;
    asm("mov.b64 %0, {%1, %1};" : "=l"(r) : "f"(x));
    return r;
}
__device__ __forceinline__ void ffma2(unsigned long long& acc,
                                      unsigned long long a, unsigned long long b) {
    asm("fma.rn.f32x2 %0, %1, %2, %0;" : "+l"(acc) : "l"(a), "l"(b));
}
__device__ __forceinline__ float2 unpack2(unsigned long long v) {
    float2 f;
    asm("mov.b64 {%0, %1}, %2;" : "=f"(f.x), "=f"(f.y) : "l"(v));
    return f;
}
__device__ __forceinline__ void red_add_v4(float* p, float a, float b, float c, float d) {
    asm volatile("red.global.add.v4.f32 [%0], {%1, %2, %3, %4};"
                 :: "l"(p), "f"(a), "f"(b), "f"(c), "f"(d) : "memory");
}

// ---------- zero the aggregation buffer ----------
__global__ void zero_hneigh_kernel(int n4) {
    int i = blockIdx.x * blockDim.x + threadIdx.x;
    if (i < n4)
        reinterpret_cast<float4*>(g_hneigh)[i] = make_float4(0.f, 0.f, 0.f, 0.f);
}

// ---------- edge message kernel ----------
// Per warp: 2 edges at a time. Lane layout: half = lane>>4 selects edge slot,
// each lane owns 8 output columns (cg = (lane&15)*8).
// m_e = relu([nfeats[src], efeats[e]] @ Wmsg + b); red.add.v4 into g_hneigh[dst].
__global__ void edge_msg_kernel(const float* __restrict__ nfeats,
                                const float* __restrict__ efeats,
                                const float* __restrict__ Wmsg,
                                const float* __restrict__ bmsg,
                                const int* __restrict__ src,
                                const int* __restrict__ dst,
                                int E)
{
    extern __shared__ float sm[];
    float* wsm  = sm;                         // 128*128 = 64 KB
    float* bsm  = wsm + D_MSG_IN * D_OUT;     // 128
    float* xall = bsm + D_OUT;                // 8 warps * 264 (2 slots * 132, padded)

    for (int i = threadIdx.x; i < (D_MSG_IN * D_OUT) / 4; i += blockDim.x)
        reinterpret_cast<float4*>(wsm)[i] = reinterpret_cast<const float4*>(Wmsg)[i];
    if (threadIdx.x < D_OUT) bsm[threadIdx.x] = bmsg[threadIdx.x];
    __syncthreads();

    const int lane = threadIdx.x & 31;
    const int warp = threadIdx.x >> 5;
    const int wpb  = blockDim.x >> 5;
    const int gw   = blockIdx.x * wpb + warp;
    const int nw   = gridDim.x * wpb;
    float* xbuf = xall + warp * 264;

    const int half = lane >> 4;        // which of the 2 edge slots
    const int cg   = (lane & 15) * 8;  // this lane's 8 output columns / staging offset

    // preload bias pairs for this lane's columns
    unsigned long long b0, b1, b2, b3;
    {
        const ulonglong2* bp = reinterpret_cast<const ulonglong2*>(bsm + cg);
        ulonglong2 p0 = bp[0], p1 = bp[1];
        b0 = p0.x; b1 = p0.y; b2 = p1.x; b3 = p1.y;
    }

    const int npairs = (E + 1) >> 1;
    for (int p = gw; p < npairs; p += nw) {
        const int e = 2 * p + half;
        const bool valid = (e < E);
        int s = 0, d = 0;
        if (valid) { s = src[e]; d = dst[e]; }

        float* xp = xbuf + half * 132;  // padded stride: avoids 2-way bank conflict

        // stage this slot's x = [nfeats[s] (64) | efeats[e] (64)], 8 floats per lane
        float4 v0, v1;
        if (valid) {
            if (cg < D_IN) {
                const float4* g = reinterpret_cast<const float4*>(nfeats + (long long)s * D_IN + cg);
                v0 = g[0]; v1 = g[1];
            } else {
                const float4* g = reinterpret_cast<const float4*>(efeats + (long long)e * D_E + (cg - D_IN));
                v0 = g[0]; v1 = g[1];
            }
        } else {
            v0 = make_float4(0.f, 0.f, 0.f, 0.f);
            v1 = v0;
        }
        *reinterpret_cast<float4*>(xp + cg)     = v0;
        *reinterpret_cast<float4*>(xp + cg + 4) = v1;
        __syncwarp();

        unsigned long long a0 = b0, a1 = b1, a2 = b2, a3 = b3;
        #pragma unroll 8
        for (int k = 0; k < D_MSG_IN; ++k) {
            unsigned long long xk = pack2(xp[k]);  // broadcast within half-warp
            const ulonglong2* wp = reinterpret_cast<const ulonglong2*>(wsm + (k << 7) + cg);
            ulonglong2 w01 = wp[0];
            ulonglong2 w23 = wp[1];
            ffma2(a0, xk, w01.x);
            ffma2(a1, xk, w01.y);
            ffma2(a2, xk, w23.x);
            ffma2(a3, xk, w23.y);
        }

        if (valid) {
            float2 f0 = unpack2(a0), f1 = unpack2(a1), f2 = unpack2(a2), f3 = unpack2(a3);
            float* hp = g_hneigh + (long long)d * D_OUT + cg;
            red_add_v4(hp,     fmaxf(f0.x, 0.f), fmaxf(f0.y, 0.f), fmaxf(f1.x, 0.f), fmaxf(f1.y, 0.f));
            red_add_v4(hp + 4, fmaxf(f2.x, 0.f), fmaxf(f2.y, 0.f), fmaxf(f3.x, 0.f), fmaxf(f3.y, 0.f));
        }
        __syncwarp();
    }
}

// ---------- apply kernel ----------
// Per warp: one node. out = relu([nfeats | h_neigh] @ Wapply + b). Lane owns 4 cols.
__global__ void apply_kernel(const float* __restrict__ nfeats,
                             const float* __restrict__ Wap,
                             const float* __restrict__ bap,
                             float* __restrict__ out,
                             int N)
{
    extern __shared__ float sm[];
    float* wsm  = sm;                          // 192*128 = 96 KB
    float* bsm  = wsm + D_APPLY_IN * D_OUT;    // 128
    float* xall = bsm + D_OUT;                 // 8 warps * 192

    for (int i = threadIdx.x; i < (D_APPLY_IN * D_OUT) / 4; i += blockDim.x)
        reinterpret_cast<float4*>(wsm)[i] = reinterpret_cast<const float4*>(Wap)[i];
    if (threadIdx.x < D_OUT) bsm[threadIdx.x] = bap[threadIdx.x];
    __syncthreads();

    const int lane = threadIdx.x & 31;
    const int warp = threadIdx.x >> 5;
    const int wpb  = blockDim.x >> 5;
    const int gw   = blockIdx.x * wpb + warp;
    const int nw   = gridDim.x * wpb;
    float* xbuf = xall + warp * D_APPLY_IN;
    const int c4 = lane * 4;

    unsigned long long b0, b1;
    {
        const ulonglong2* bp = reinterpret_cast<const ulonglong2*>(bsm + c4);
        ulonglong2 p = bp[0];
        b0 = p.x; b1 = p.y;
    }

    for (int node = gw; node < N; node += nw) {
        if (lane < 16)
            *reinterpret_cast<float4*>(xbuf + lane * 4) =
                *reinterpret_cast<const float4*>(nfeats + (long long)node * D_IN + lane * 4);
        *reinterpret_cast<float4*>(xbuf + D_IN + lane * 4) =
            *reinterpret_cast<const float4*>(g_hneigh + (long long)node * D_OUT + lane * 4);
        __syncwarp();

        unsigned long long a0 = b0, a1 = b1;
        #pragma unroll 8
        for (int k = 0; k < D_APPLY_IN; ++k) {
            unsigned long long xk = pack2(xbuf[k]);
            const ulonglong2* wp = reinterpret_cast<const ulonglong2*>(wsm + (k << 7) + c4);
            ulonglong2 w = wp[0];
            ffma2(a0, xk, w.x);
            ffma2(a1, xk, w.y);
        }
        float2 f0 = unpack2(a0), f1 = unpack2(a1);
        float4 o = make_float4(fmaxf(f0.x, 0.f), fmaxf(f0.y, 0.f),
                               fmaxf(f1.x, 0.f), fmaxf(f1.y, 0.f));
        *reinterpret_cast<float4*>(out + (long long)node * D_OUT + c4) = o;
        __syncwarp();
    }
}

extern "C" void kernel_launch(void* const* d_in, const int* in_sizes, int n_in,
                              void* d_out, int out_size)
{
    const float* nfeats = (const float*)d_in[0];
    const float* efeats = (const float*)d_in[1];
    const float* Wmsg   = (const float*)d_in[2];
    const float* bmsg   = (const float*)d_in[3];
    const float* Wap    = (const float*)d_in[4];
    const float* bap    = (const float*)d_in[5];
    const int*   src    = (const int*)d_in[6];   // JAX default x64 disabled -> int32
    const int*   dst    = (const int*)d_in[7];

    const int E = in_sizes[6];
    const int N = in_sizes[0] / D_IN;

    const size_t smem_edge  = (size_t)(D_MSG_IN * D_OUT + D_OUT + 8 * 264) * sizeof(float);
    const size_t smem_apply = (size_t)(D_APPLY_IN * D_OUT + D_OUT + 8 * D_APPLY_IN) * sizeof(float);
    cudaFuncSetAttribute(edge_msg_kernel, cudaFuncAttributeMaxDynamicSharedMemorySize, (int)smem_edge);
    cudaFuncSetAttribute(apply_kernel,    cudaFuncAttributeMaxDynamicSharedMemorySize, (int)smem_apply);

    const int n4 = (N * D_OUT) / 4;
    zero_hneigh_kernel<<<(n4 + 255) / 256, 256>>>(n4);
    edge_msg_kernel<<<888, 256, smem_edge>>>(nfeats, efeats, Wmsg, bmsg, src, dst, E);
    apply_kernel<<<592, 256, smem_apply>>>(nfeats, Wap, bap, (float*)d_out, N);
}

// round 3
// speedup vs baseline: 4.4313x; 4.4313x over previous
#include <cuda_runtime.h>

#define D_IN 64
#define D_E 64
#define D_MSG_IN 128
#define D_OUT 128
#define D_APPLY_IN 192
#define MAX_NODES 50000

__device__ float g_hneigh[MAX_NODES * D_OUT];

// ---------- packed f32x2 helpers ----------
__device__ __forceinline__ void ffma2(unsigned long long& acc,
                                      unsigned long long a, unsigned long long b) {
    asm("fma.rn.f32x2 %0, %1, %2, %0;" : "+l"(acc) : "l"(a), "l"(b));
}
__device__ __forceinline__ float2 unpack2(unsigned long long v) {
    float2 f;
    asm("mov.b64 {%0, %1}, %2;" : "=f"(f.x), "=f"(f.y) : "l"(v));
    return f;
}
__device__ __forceinline__ void red_add_v4(float* p, float a, float b, float c, float d) {
    asm volatile("red.global.add.v4.f32 [%0], {%1, %2, %3, %4};"
                 :: "l"(p), "f"(a), "f"(b), "f"(c), "f"(d) : "memory");
}

__global__ void zero_hneigh_kernel(int n4) {
    int i = blockIdx.x * blockDim.x + threadIdx.x;
    if (i < n4)
        reinterpret_cast<float4*>(g_hneigh)[i] = make_float4(0.f, 0.f, 0.f, 0.f);
}

// =====================================================================
// Edge message kernel v2: 8 edges per warp, f32x2 packed along k,
// W transposed+swizzled in smem (each W row read once per 8 edges).
// =====================================================================
// smem layout (floats):
//   [0, 16384)        Wt  : Wt[c][k] swizzled: addr = c*128 + ((k>>2)^((c>>2)&7))*4 + (k&3)
//   [16384, 16512)    bias
//   [16512, 24960)    x   : 8 warps * 8 edges * 132 (row-major, padded)
#define E_WT 0
#define E_BIAS 16384
#define E_X 16512
#define E_SMEM_FLOATS 24960

__global__ __launch_bounds__(256, 2)
void edge_msg_kernel(const float* __restrict__ nfeats,
                     const float* __restrict__ efeats,
                     const float* __restrict__ Wmsg,
                     const float* __restrict__ bmsg,
                     const int* __restrict__ src,
                     const int* __restrict__ dst,
                     int E)
{
    extern __shared__ float sm[];
    float* wsm  = sm + E_WT;
    float* bsm  = sm + E_BIAS;
    float* xall = sm + E_X;

    // --- transpose W (128x128) into swizzled Wt, staged via x area ---
    for (int half = 0; half < 2; ++half) {
        for (int i = threadIdx.x; i < 2048; i += 256)
            reinterpret_cast<float4*>(xall)[i] =
                reinterpret_cast<const float4*>(Wmsg + half * 8192)[i];
        __syncthreads();
        for (int i = threadIdx.x; i < 8192; i += 256) {
            int kl = i >> 7, c = i & 127, k = half * 64 + kl;
            wsm[(c << 7) + (((k >> 2) ^ ((c >> 2) & 7)) << 2) + (k & 3)] = xall[i];
        }
        __syncthreads();
    }
    if (threadIdx.x < 128) bsm[threadIdx.x] = bmsg[threadIdx.x];
    __syncthreads();

    const int lane = threadIdx.x & 31;
    const int warp = threadIdx.x >> 5;
    const int gw   = blockIdx.x * 8 + warp;
    const int nw   = gridDim.x * 8;
    const int s7   = lane & 7;

    float* xw = xall + warp * (8 * 132);
    const float* wl = wsm + ((lane * 4) << 7);       // col base: c = 4*lane
    const float4 bias4 = *reinterpret_cast<const float4*>(bsm + lane * 4);

    const int h  = lane >> 4;
    const int j  = lane & 15;
    const int cg = j * 8;

    unsigned long long acc[8][4];
    #pragma unroll
    for (int e = 0; e < 8; ++e)
        #pragma unroll
        for (int c = 0; c < 4; ++c) acc[e][c] = 0ull;

    const int tiles = (E + 7) >> 3;
    for (int tile = gw; tile < tiles; tile += nw) {
        const int base = tile * 8;

        // indices: lanes 0-7 hold src/dst for the 8 edges
        int sv = 0, dv = 0;
        if (lane < 8) {
            int e = base + lane;
            if (e < E) { sv = src[e]; dv = dst[e]; }
        }

        // gather 8 edge rows (4 rounds x 2 edges), row-major into xw
        #pragma unroll
        for (int r = 0; r < 4; ++r) {
            int el = r * 2 + h;
            int eg = base + el;
            int se = __shfl_sync(0xffffffffu, sv, el);
            float4 v0, v1;
            if (eg < E) {
                if (cg < D_IN) {
                    const float4* g = reinterpret_cast<const float4*>(nfeats + (size_t)se * D_IN + cg);
                    v0 = g[0]; v1 = g[1];
                } else {
                    const float4* g = reinterpret_cast<const float4*>(efeats + (size_t)eg * D_E + (cg - D_IN));
                    v0 = g[0]; v1 = g[1];
                }
            } else {
                v0 = make_float4(0.f, 0.f, 0.f, 0.f); v1 = v0;
            }
            *reinterpret_cast<float4*>(xw + el * 132 + cg)     = v0;
            *reinterpret_cast<float4*>(xw + el * 132 + cg + 4) = v1;
        }
        __syncwarp();

        // inner GEMM: 32 k-chunks of 4
        #pragma unroll 4
        for (int t = 0; t < 32; ++t) {
            const int wq = ((t ^ s7) << 2);   // swizzled chunk offset (floats)
            ulonglong2 w0 = *reinterpret_cast<const ulonglong2*>(wl + wq);
            ulonglong2 w1 = *reinterpret_cast<const ulonglong2*>(wl + 128 + wq);
            ulonglong2 w2 = *reinterpret_cast<const ulonglong2*>(wl + 256 + wq);
            ulonglong2 w3 = *reinterpret_cast<const ulonglong2*>(wl + 384 + wq);
            #pragma unroll
            for (int e = 0; e < 8; ++e) {
                ulonglong2 xv = *reinterpret_cast<const ulonglong2*>(xw + e * 132 + t * 4);
                ffma2(acc[e][0], xv.x, w0.x); ffma2(acc[e][0], xv.y, w0.y);
                ffma2(acc[e][1], xv.x, w1.x); ffma2(acc[e][1], xv.y, w1.y);
                ffma2(acc[e][2], xv.x, w2.x); ffma2(acc[e][2], xv.y, w2.y);
                ffma2(acc[e][3], xv.x, w3.x); ffma2(acc[e][3], xv.y, w3.y);
            }
        }

        // epilogue: horizontal add, bias, relu, scatter-add
        #pragma unroll
        for (int e = 0; e < 8; ++e) {
            int eg = base + e;
            int de = __shfl_sync(0xffffffffu, dv, e);
            float2 f0 = unpack2(acc[e][0]);
            float2 f1 = unpack2(acc[e][1]);
            float2 f2 = unpack2(acc[e][2]);
            float2 f3 = unpack2(acc[e][3]);
            float o0 = fmaxf(f0.x + f0.y + bias4.x, 0.f);
            float o1 = fmaxf(f1.x + f1.y + bias4.y, 0.f);
            float o2 = fmaxf(f2.x + f2.y + bias4.z, 0.f);
            float o3 = fmaxf(f3.x + f3.y + bias4.w, 0.f);
            if (eg < E)
                red_add_v4(g_hneigh + (size_t)de * D_OUT + lane * 4, o0, o1, o2, o3);
            acc[e][0] = 0ull; acc[e][1] = 0ull; acc[e][2] = 0ull; acc[e][3] = 0ull;
        }
        __syncwarp();
    }
}

// =====================================================================
// Apply kernel v2: 8 nodes per warp, same f32x2-along-k scheme.
// =====================================================================
// smem layout (floats):
//   [0, 24576)         WtA : addr = c*192 + ((k>>2)^((c>>2)&7))*4 + (k&3)
//   [24576, 24704)     bias
//   [24704, 37248)     x   : 8 warps * 8 nodes * 196
#define A_WT 0
#define A_BIAS 24576
#define A_X 24704
#define A_SMEM_FLOATS 37248

__global__ __launch_bounds__(256, 1)
void apply_kernel(const float* __restrict__ nfeats,
                  const float* __restrict__ Wap,
                  const float* __restrict__ bap,
                  float* __restrict__ out,
                  int N)
{
    extern __shared__ float sm[];
    float* wsm  = sm + A_WT;
    float* bsm  = sm + A_BIAS;
    float* xall = sm + A_X;

    // --- transpose W_apply (192x128) into swizzled WtA, staged via x area ---
    for (int half = 0; half < 2; ++half) {
        for (int i = threadIdx.x; i < 3072; i += 256)
            reinterpret_cast<float4*>(xall)[i] =
                reinterpret_cast<const float4*>(Wap + half * 12288)[i];
        __syncthreads();
        for (int i = threadIdx.x; i < 12288; i += 256) {
            int kl = i >> 7, c = i & 127, k = half * 96 + kl;
            wsm[c * 192 + (((k >> 2) ^ ((c >> 2) & 7)) << 2) + (k & 3)] = xall[i];
        }
        __syncthreads();
    }
    if (threadIdx.x < 128) bsm[threadIdx.x] = bap[threadIdx.x];
    __syncthreads();

    const int lane = threadIdx.x & 31;
    const int warp = threadIdx.x >> 5;
    const int gw   = blockIdx.x * 8 + warp;
    const int nw   = gridDim.x * 8;
    const int s7   = lane & 7;

    float* xw = xall + warp * (8 * 196);
    const float* wl = wsm + (lane * 4) * 192;
    const float4 bias4 = *reinterpret_cast<const float4*>(bsm + lane * 4);

    const int h  = lane >> 4;
    const int j  = lane & 15;
    const int cg = j * 12;

    unsigned long long acc[8][4];
    #pragma unroll
    for (int e = 0; e < 8; ++e)
        #pragma unroll
        for (int c = 0; c < 4; ++c) acc[e][c] = 0ull;

    const int tiles = (N + 7) >> 3;
    for (int tile = gw; tile < tiles; tile += nw) {
        const int base = tile * 8;

        // gather 8 node rows: [nfeats(64) | g_hneigh(128)] = 192 floats
        #pragma unroll
        for (int r = 0; r < 4; ++r) {
            int nl = r * 2 + h;
            int ng = base + nl;
            if (ng < N) {
                #pragma unroll
                for (int q = 0; q < 3; ++q) {
                    int off = cg + q * 4;
                    float4 v;
                    if (off < D_IN)
                        v = *reinterpret_cast<const float4*>(nfeats + (size_t)ng * D_IN + off);
                    else
                        v = *reinterpret_cast<const float4*>(g_hneigh + (size_t)ng * D_OUT + (off - D_IN));
                    *reinterpret_cast<float4*>(xw + nl * 196 + off) = v;
                }
            }
        }
        __syncwarp();

        // inner GEMM: 48 k-chunks of 4
        #pragma unroll 4
        for (int t = 0; t < 48; ++t) {
            const int wq = ((t ^ s7) << 2);
            ulonglong2 w0 = *reinterpret_cast<const ulonglong2*>(wl + wq);
            ulonglong2 w1 = *reinterpret_cast<const ulonglong2*>(wl + 192 + wq);
            ulonglong2 w2 = *reinterpret_cast<const ulonglong2*>(wl + 384 + wq);
            ulonglong2 w3 = *reinterpret_cast<const ulonglong2*>(wl + 576 + wq);
            #pragma unroll
            for (int e = 0; e < 8; ++e) {
                ulonglong2 xv = *reinterpret_cast<const ulonglong2*>(xw + e * 196 + t * 4);
                ffma2(acc[e][0], xv.x, w0.x); ffma2(acc[e][0], xv.y, w0.y);
                ffma2(acc[e][1], xv.x, w1.x); ffma2(acc[e][1], xv.y, w1.y);
                ffma2(acc[e][2], xv.x, w2.x); ffma2(acc[e][2], xv.y, w2.y);
                ffma2(acc[e][3], xv.x, w3.x); ffma2(acc[e][3], xv.y, w3.y);
            }
        }

        // epilogue: plain coalesced store
        #pragma unroll
        for (int e = 0; e < 8; ++e) {
            int ng = base + e;
            float2 f0 = unpack2(acc[e][0]);
            float2 f1 = unpack2(acc[e][1]);
            float2 f2 = unpack2(acc[e][2]);
            float2 f3 = unpack2(acc[e][3]);
            float4 o;
            o.x = fmaxf(f0.x + f0.y + bias4.x, 0.f);
            o.y = fmaxf(f1.x + f1.y + bias4.y, 0.f);
            o.z = fmaxf(f2.x + f2.y + bias4.z, 0.f);
            o.w = fmaxf(f3.x + f3.y + bias4.w, 0.f);
            if (ng < N)
                *reinterpret_cast<float4*>(out + (size_t)ng * D_OUT + lane * 4) = o;
            acc[e][0] = 0ull; acc[e][1] = 0ull; acc[e][2] = 0ull; acc[e][3] = 0ull;
        }
        __syncwarp();
    }
}

extern "C" void kernel_launch(void* const* d_in, const int* in_sizes, int n_in,
                              void* d_out, int out_size)
{
    const float* nfeats = (const float*)d_in[0];
    const float* efeats = (const float*)d_in[1];
    const float* Wmsg   = (const float*)d_in[2];
    const float* bmsg   = (const float*)d_in[3];
    const float* Wap    = (const float*)d_in[4];
    const float* bap    = (const float*)d_in[5];
    const int*   src    = (const int*)d_in[6];
    const int*   dst    = (const int*)d_in[7];

    const int E = in_sizes[6];
    const int N = in_sizes[0] / D_IN;

    const size_t smem_edge  = E_SMEM_FLOATS * sizeof(float);   // 99840 B
    const size_t smem_apply = A_SMEM_FLOATS * sizeof(float);   // 148992 B
    cudaFuncSetAttribute(edge_msg_kernel, cudaFuncAttributeMaxDynamicSharedMemorySize, (int)smem_edge);
    cudaFuncSetAttribute(apply_kernel,    cudaFuncAttributeMaxDynamicSharedMemorySize, (int)smem_apply);

    const int n4 = (N * D_OUT) / 4;
    zero_hneigh_kernel<<<(n4 + 255) / 256, 256>>>(n4);
    edge_msg_kernel<<<304, 256, smem_edge>>>(nfeats, efeats, Wmsg, bmsg, src, dst, E);
    apply_kernel<<<152, 256, smem_apply>>>(nfeats, Wap, bap, (float*)d_out, N);
}